// round 1
// baseline (speedup 1.0000x reference)
#include <cuda_runtime.h>

#define Bv 8
#define Tv 2048
#define Cv 768
#define Hv 64
#define LDK 65

// Scratch for q = x @ Wq  (4 MB). __device__ global: allocation-guard safe.
__device__ float g_q[Bv * Tv * Hv];

// ---------------------------------------------------------------------------
// Kernel 1: q[B*T, 64] = x[B*T, 768] @ Wq[768, 64]
// 64-row tiles, 256 threads, 4x4 register micro-tile per thread.
// ---------------------------------------------------------------------------
__global__ __launch_bounds__(256) void qproj_kernel(const float* __restrict__ x,
                                                    const float* __restrict__ Wq) {
    __shared__ float As[64 * 64];
    __shared__ float Bs[64 * 64];
    const int t = threadIdx.x;
    const int tx = t & 15, ty = t >> 4;
    const int row0 = blockIdx.x * 64;

    float acc[4][4] = {};
    for (int kk = 0; kk < Cv; kk += 64) {
#pragma unroll
        for (int i = 0; i < 16; i++) {
            int idx = t + i * 256;
            int r = idx >> 6, c = idx & 63;
            As[idx] = x[(size_t)(row0 + r) * Cv + kk + c];
            Bs[idx] = Wq[(size_t)(kk + r) * Hv + c];
        }
        __syncthreads();
#pragma unroll 16
        for (int k = 0; k < 64; k++) {
            float a[4], b[4];
#pragma unroll
            for (int i = 0; i < 4; i++) a[i] = As[(ty * 4 + i) * 64 + k];
#pragma unroll
            for (int j = 0; j < 4; j++) b[j] = Bs[k * 64 + tx + 16 * j];
#pragma unroll
            for (int i = 0; i < 4; i++)
#pragma unroll
                for (int j = 0; j < 4; j++)
                    acc[i][j] += a[i] * b[j];
        }
        __syncthreads();
    }
#pragma unroll
    for (int i = 0; i < 4; i++)
#pragma unroll
        for (int j = 0; j < 4; j++)
            g_q[(size_t)(row0 + ty * 4 + i) * Hv + tx + 16 * j] = acc[i][j];
}

// ---------------------------------------------------------------------------
// Kernel 2: flash attention with q = k = v, causal + relative bias.
// Block = one (batch, 64-query tile). 256 threads, 4x4 register tiles.
// K smem tile doubles as the V tile (k == v).
// ---------------------------------------------------------------------------
__global__ __launch_bounds__(256) void attn_kernel(const float* __restrict__ rel,
                                                   float* __restrict__ out) {
    extern __shared__ float smem[];
    float* Qs   = smem;                  // 64*64
    float* Ks   = Qs + 64 * 64;          // 64*LDK (padded: conflict-free reads)
    float* Ps   = Ks + 64 * LDK;         // 64*LDK
    float* bias = Ps + 64 * LDK;         // 128

    const int t = threadIdx.x;
    const int tx = t & 15, ty = t >> 4;
    const int qt = blockIdx.x;           // query tile 0..31
    const int b  = blockIdx.y;
    const float* qbase = g_q + (size_t)b * Tv * Hv;

    // Load Q tile (contiguous 64x64)
#pragma unroll
    for (int i = 0; i < 16; i++) {
        int idx = t + i * 256;
        Qs[idx] = qbase[(size_t)(qt * 64) * Hv + idx];
    }

    float m[4], l[4], acc[4][4];
#pragma unroll
    for (int i = 0; i < 4; i++) {
        m[i] = -1e30f; l[i] = 0.f;
#pragma unroll
        for (int j = 0; j < 4; j++) acc[i][j] = 0.f;
    }

    for (int kt = 0; kt <= qt; kt++) {
        __syncthreads();  // previous PV done before Ks overwrite (covers Qs too on iter 0)
        // Load K tile (== V tile), padded rows
#pragma unroll
        for (int i = 0; i < 16; i++) {
            int idx = t + i * 256;
            int r = idx >> 6, c = idx & 63;
            Ks[r * LDK + c] = qbase[(size_t)(kt * 64 + r) * Hv + c];
        }
        // Bias slice: d = s - t spans 127 values for this tile pair
        if (t < 127) bias[t] = rel[(kt - qt) * 64 - 63 + 2047 + t];
        __syncthreads();

        // ---- S = Q @ K^T ----
        float s[4][4] = {};
#pragma unroll 8
        for (int k = 0; k < 64; k++) {
            float a[4], kb[4];
#pragma unroll
            for (int i = 0; i < 4; i++) a[i] = Qs[(ty * 4 + i) * 64 + k];
#pragma unroll
            for (int j = 0; j < 4; j++) kb[j] = Ks[(tx + 16 * j) * LDK + k];
#pragma unroll
            for (int i = 0; i < 4; i++)
#pragma unroll
                for (int j = 0; j < 4; j++)
                    s[i][j] += a[i] * kb[j];
        }

        // scale + bias + causal mask (only diagonal tile needs masking)
        const bool diag = (kt == qt);
        float mloc[4];
#pragma unroll
        for (int i = 0; i < 4; i++) {
            const int r = ty * 4 + i;
            mloc[i] = -1e30f;
#pragma unroll
            for (int j = 0; j < 4; j++) {
                const int c = tx + 16 * j;
                float v = s[i][j] * 0.125f + bias[c - r + 63];
                if (diag && c > r) v = -1e30f;
                s[i][j] = v;
                mloc[i] = fmaxf(mloc[i], v);
            }
        }
        // row max over the 16-lane row group
#pragma unroll
        for (int off = 1; off < 16; off <<= 1)
#pragma unroll
            for (int i = 0; i < 4; i++)
                mloc[i] = fmaxf(mloc[i], __shfl_xor_sync(0xffffffffu, mloc[i], off));

        float rs[4];
#pragma unroll
        for (int i = 0; i < 4; i++) {
            const float mnew  = fmaxf(m[i], mloc[i]);
            const float alpha = __expf(m[i] - mnew);
            m[i] = mnew;
            float sum = 0.f;
#pragma unroll
            for (int j = 0; j < 4; j++) {
                const float p = __expf(s[i][j] - mnew);
                sum += p;
                Ps[(ty * 4 + i) * LDK + tx + 16 * j] = p;
            }
            rs[i] = sum;
            l[i] *= alpha;
#pragma unroll
            for (int j = 0; j < 4; j++) acc[i][j] *= alpha;
        }
#pragma unroll
        for (int off = 1; off < 16; off <<= 1)
#pragma unroll
            for (int i = 0; i < 4; i++)
                rs[i] += __shfl_xor_sync(0xffffffffu, rs[i], off);
#pragma unroll
        for (int i = 0; i < 4; i++) l[i] += rs[i];

        __syncthreads();  // Ps fully written

        // ---- O += P @ V  (V = Ks) ----
#pragma unroll 8
        for (int c = 0; c < 64; c++) {
            float p[4], v[4];
#pragma unroll
            for (int i = 0; i < 4; i++) p[i] = Ps[(ty * 4 + i) * LDK + c];
#pragma unroll
            for (int j = 0; j < 4; j++) v[j] = Ks[c * LDK + tx + 16 * j];
#pragma unroll
            for (int i = 0; i < 4; i++)
#pragma unroll
                for (int j = 0; j < 4; j++)
                    acc[i][j] += p[i] * v[j];
        }
    }

    // Final normalize + store
#pragma unroll
    for (int i = 0; i < 4; i++) {
        const float inv = 1.f / l[i];
#pragma unroll
        for (int j = 0; j < 4; j++)
            out[((size_t)b * Tv + qt * 64 + ty * 4 + i) * Hv + tx + 16 * j] = acc[i][j] * inv;
    }
}

// ---------------------------------------------------------------------------
extern "C" void kernel_launch(void* const* d_in, const int* in_sizes, int n_in,
                              void* d_out, int out_size) {
    const float* x   = (const float*)d_in[0];   // [8, 2048, 768]
    const float* Wq  = (const float*)d_in[1];   // [768, 64]
    const float* rel = (const float*)d_in[2];   // [4095, 1]
    float* out = (float*)d_out;                 // [8, 2048, 64] fp32

    const int smem_bytes = (64 * 64 + 2 * 64 * LDK + 128) * sizeof(float);  // 50176
    cudaFuncSetAttribute(attn_kernel, cudaFuncAttributeMaxDynamicSharedMemorySize, smem_bytes);

    qproj_kernel<<<Bv * Tv / 64, 256>>>(x, Wq);

    dim3 grid(Tv / 64, Bv);
    attn_kernel<<<grid, 256, smem_bytes>>>(rel, out);
}

// round 3
// speedup vs baseline: 1.4504x; 1.4504x over previous
#include <cuda_runtime.h>

#define Bv 8
#define Tv 2048
#define Cv 768
#define Hv 64
#define LDK 65
#define NCH 4          // max KV chunks per query tile (32 key-tiles / 8)
#define CHT 8          // key-tiles per chunk

// ---- scratch (__device__ globals: allocation-guard safe) ----
__device__ float g_qp[3][Bv * Tv * Hv];            // qproj split-K partials (12 MB)
__device__ float g_q[Bv * Tv * Hv];                // q = x @ Wq            (4 MB)
__device__ float g_pacc[Bv * 32 * NCH * 64 * 64];  // attn partial O        (16 MB)
__device__ float g_pml[Bv * 32 * NCH * 64 * 2];    // attn partial (m, l)

// ---------------------------------------------------------------------------
// Kernel 1: split-K q-projection. part p covers k in [p*256, p*256+256).
// ---------------------------------------------------------------------------
__global__ __launch_bounds__(256) void qproj_part(const float* __restrict__ x,
                                                  const float* __restrict__ Wq) {
    __shared__ float As[64 * 64];
    __shared__ float Bs[64 * 64];
    const int t = threadIdx.x;
    const int tx = t & 15, ty = t >> 4;
    const int row0 = blockIdx.x * 64;
    const int part = blockIdx.y;

    float acc[4][4] = {};
    const int kk0 = part * 256;
    for (int kk = kk0; kk < kk0 + 256; kk += 64) {
#pragma unroll
        for (int i = 0; i < 16; i++) {
            int idx = t + i * 256;
            int r = idx >> 6, c = idx & 63;
            As[idx] = x[(size_t)(row0 + r) * Cv + kk + c];
            Bs[idx] = Wq[(size_t)(kk + r) * Hv + c];
        }
        __syncthreads();
#pragma unroll 16
        for (int k = 0; k < 64; k++) {
            float a[4], b[4];
#pragma unroll
            for (int i = 0; i < 4; i++) a[i] = As[(ty * 4 + i) * 64 + k];
#pragma unroll
            for (int j = 0; j < 4; j++) b[j] = Bs[k * 64 + tx + 16 * j];
#pragma unroll
            for (int i = 0; i < 4; i++)
#pragma unroll
                for (int j = 0; j < 4; j++)
                    acc[i][j] += a[i] * b[j];
        }
        __syncthreads();
    }
#pragma unroll
    for (int i = 0; i < 4; i++)
#pragma unroll
        for (int j = 0; j < 4; j++)
            g_qp[part][(size_t)(row0 + ty * 4 + i) * Hv + tx + 16 * j] = acc[i][j];
}

// ---------------------------------------------------------------------------
// Kernel 2: reduce the 3 split-K partials (vectorized float4).
// ---------------------------------------------------------------------------
__global__ __launch_bounds__(256) void qproj_reduce() {
    const int i = blockIdx.x * 256 + threadIdx.x;   // float4 index
    const float4 a = ((const float4*)g_qp[0])[i];
    const float4 b = ((const float4*)g_qp[1])[i];
    const float4 c = ((const float4*)g_qp[2])[i];
    float4 r;
    r.x = a.x + b.x + c.x;  r.y = a.y + b.y + c.y;
    r.z = a.z + b.z + c.z;  r.w = a.w + b.w + c.w;
    ((float4*)g_q)[i] = r;
}

// ---------------------------------------------------------------------------
// Kernel 3: split-KV flash attention chunk. Block = (qt, b, chunk).
// Writes unnormalized partial O and (m, l) per row.
// ---------------------------------------------------------------------------
__global__ __launch_bounds__(256) void attn_chunk(const float* __restrict__ rel) {
    extern __shared__ float smem[];
    float* Qs   = smem;                  // 64*64
    float* Ks   = Qs + 64 * 64;          // 64*LDK
    float* Ps   = Ks + 64 * LDK;         // 64*LDK
    float* bias = Ps + 64 * LDK;         // 128

    const int qt = blockIdx.x;
    const int b  = blockIdx.y;
    const int ch = blockIdx.z;
    const int nch = (qt >> 3) + 1;
    if (ch >= nch) return;

    const int t = threadIdx.x;
    const int tx = t & 15, ty = t >> 4;
    const float* qbase = g_q + (size_t)b * Tv * Hv;

#pragma unroll
    for (int i = 0; i < 16; i++) {
        int idx = t + i * 256;
        Qs[idx] = qbase[(size_t)(qt * 64) * Hv + idx];
    }

    float m[4], l[4], acc[4][4];
#pragma unroll
    for (int i = 0; i < 4; i++) {
        m[i] = -1e30f; l[i] = 0.f;
#pragma unroll
        for (int j = 0; j < 4; j++) acc[i][j] = 0.f;
    }

    const int kt0 = ch * CHT;
    const int kt1 = min(kt0 + CHT - 1, qt);

    for (int kt = kt0; kt <= kt1; kt++) {
        __syncthreads();
#pragma unroll
        for (int i = 0; i < 16; i++) {
            int idx = t + i * 256;
            int r = idx >> 6, c = idx & 63;
            Ks[r * LDK + c] = qbase[(size_t)(kt * 64 + r) * Hv + c];
        }
        if (t < 127) bias[t] = rel[(kt - qt) * 64 - 63 + 2047 + t];
        __syncthreads();

        // ---- S = Q @ K^T ----
        float s[4][4] = {};
#pragma unroll 8
        for (int k = 0; k < 64; k++) {
            float a[4], kb[4];
#pragma unroll
            for (int i = 0; i < 4; i++) a[i] = Qs[(ty * 4 + i) * 64 + k];
#pragma unroll
            for (int j = 0; j < 4; j++) kb[j] = Ks[(tx + 16 * j) * LDK + k];
#pragma unroll
            for (int i = 0; i < 4; i++)
#pragma unroll
                for (int j = 0; j < 4; j++)
                    s[i][j] += a[i] * kb[j];
        }

        const bool diag = (kt == qt);
        float mloc[4];
#pragma unroll
        for (int i = 0; i < 4; i++) {
            const int r = ty * 4 + i;
            mloc[i] = -1e30f;
#pragma unroll
            for (int j = 0; j < 4; j++) {
                const int c = tx + 16 * j;
                float v = s[i][j] * 0.125f + bias[c - r + 63];
                if (diag && c > r) v = -1e30f;
                s[i][j] = v;
                mloc[i] = fmaxf(mloc[i], v);
            }
        }
#pragma unroll
        for (int off = 1; off < 16; off <<= 1)
#pragma unroll
            for (int i = 0; i < 4; i++)
                mloc[i] = fmaxf(mloc[i], __shfl_xor_sync(0xffffffffu, mloc[i], off));

        float rs[4];
#pragma unroll
        for (int i = 0; i < 4; i++) {
            const float mnew  = fmaxf(m[i], mloc[i]);
            const float alpha = __expf(m[i] - mnew);
            m[i] = mnew;
            float sum = 0.f;
#pragma unroll
            for (int j = 0; j < 4; j++) {
                const float p = __expf(s[i][j] - mnew);
                sum += p;
                Ps[(ty * 4 + i) * LDK + tx + 16 * j] = p;
            }
            rs[i] = sum;
            l[i] *= alpha;
#pragma unroll
            for (int j = 0; j < 4; j++) acc[i][j] *= alpha;
        }
#pragma unroll
        for (int off = 1; off < 16; off <<= 1)
#pragma unroll
            for (int i = 0; i < 4; i++)
                rs[i] += __shfl_xor_sync(0xffffffffu, rs[i], off);
#pragma unroll
        for (int i = 0; i < 4; i++) l[i] += rs[i];

        __syncthreads();

        // ---- O += P @ V  (V = Ks, since k == v == q) ----
#pragma unroll 8
        for (int c = 0; c < 64; c++) {
            float p[4], v[4];
#pragma unroll
            for (int i = 0; i < 4; i++) p[i] = Ps[(ty * 4 + i) * LDK + c];
#pragma unroll
            for (int j = 0; j < 4; j++) v[j] = Ks[c * LDK + tx + 16 * j];
#pragma unroll
            for (int i = 0; i < 4; i++)
#pragma unroll
                for (int j = 0; j < 4; j++)
                    acc[i][j] += p[i] * v[j];
        }
    }

    // ---- write partials (unnormalized) ----
    const size_t slot = ((size_t)(b * 32 + qt) * NCH + ch);
    float* pacc = g_pacc + slot * 4096;
    float* pml  = g_pml  + slot * 128;
#pragma unroll
    for (int i = 0; i < 4; i++) {
#pragma unroll
        for (int j = 0; j < 4; j++)
            pacc[(ty * 4 + i) * 64 + tx + 16 * j] = acc[i][j];
        if (tx == 0) {
            pml[(ty * 4 + i) * 2 + 0] = m[i];
            pml[(ty * 4 + i) * 2 + 1] = l[i];
        }
    }
}

// ---------------------------------------------------------------------------
// Kernel 4: combine chunk partials -> final output.
// ---------------------------------------------------------------------------
__global__ __launch_bounds__(256) void attn_combine(float* __restrict__ out) {
    __shared__ float ws[NCH][64];
    const int qt = blockIdx.x;
    const int b  = blockIdx.y;
    const int nch = (qt >> 3) + 1;
    const int t = threadIdx.x;
    const size_t base = (size_t)(b * 32 + qt) * NCH;

    if (t < 64) {
        float mm[NCH], ll[NCH];
        float M = -1e30f;
        for (int c = 0; c < nch; c++) {
            mm[c] = g_pml[(base + c) * 128 + t * 2 + 0];
            ll[c] = g_pml[(base + c) * 128 + t * 2 + 1];
            M = fmaxf(M, mm[c]);
        }
        float L = 0.f;
        for (int c = 0; c < nch; c++) L += __expf(mm[c] - M) * ll[c];
        const float inv = 1.f / L;
        for (int c = 0; c < nch; c++) ws[c][t] = __expf(mm[c] - M) * inv;
    }
    __syncthreads();

    float* obase = out + ((size_t)b * Tv + qt * 64) * Hv;
#pragma unroll
    for (int i = 0; i < 16; i++) {
        const int idx = t + i * 256;
        const int r = idx >> 6;
        float s = 0.f;
        for (int c = 0; c < nch; c++)
            s += g_pacc[(base + c) * 4096 + idx] * ws[c][r];
        obase[idx] = s;
    }
}

// ---------------------------------------------------------------------------
extern "C" void kernel_launch(void* const* d_in, const int* in_sizes, int n_in,
                              void* d_out, int out_size) {
    const float* x   = (const float*)d_in[0];   // [8, 2048, 768]
    const float* Wq  = (const float*)d_in[1];   // [768, 64]
    const float* rel = (const float*)d_in[2];   // [4095, 1]
    float* out = (float*)d_out;                 // [8, 2048, 64]

    const int smem_bytes = (64 * 64 + 2 * 64 * LDK + 128) * sizeof(float);  // 50176
    cudaFuncSetAttribute(attn_chunk, cudaFuncAttributeMaxDynamicSharedMemorySize, smem_bytes);

    qproj_part<<<dim3(Bv * Tv / 64, 3), 256>>>(x, Wq);
    qproj_reduce<<<(Bv * Tv * Hv / 4) / 256, 256>>>();
    attn_chunk<<<dim3(Tv / 64, Bv, NCH), 256, smem_bytes>>>(rel);
    attn_combine<<<dim3(Tv / 64, Bv), 256>>>(out);
}

// round 4
// speedup vs baseline: 1.5526x; 1.0705x over previous
#include <cuda_runtime.h>

#define Bv 8
#define Tv 2048
#define Cv 768
#define Hv 64
#define LDT 68         // padded stride (floats): 16B-aligned, good bank spread
#define NCH 4
#define CHT 8

// ---- scratch (__device__ globals: allocation-guard safe) ----
__device__ float g_qp[3][Bv * Tv * Hv];
__device__ float g_q[Bv * Tv * Hv];
__device__ float g_pacc[Bv * 32 * NCH * 64 * 64];
__device__ float g_pml[Bv * 32 * NCH * 64 * 2];

// ---------------------------------------------------------------------------
// Kernel 1: split-K q-projection, float4 loads, transposed-A LDS.128 reads.
// ---------------------------------------------------------------------------
__global__ __launch_bounds__(256) void qproj_part(const float* __restrict__ x,
                                                  const float* __restrict__ Wq) {
    __shared__ float AsT[64 * LDT];   // AsT[k][r]
    __shared__ float Bs[64 * 64];     // Bs[k][c]
    const int t = threadIdx.x;
    const int tx = t & 15, ty = t >> 4;
    const int row0 = blockIdx.x * 64;
    const int part = blockIdx.y;

    float acc[4][4] = {};
    const int kk0 = part * 256;
    for (int kk = kk0; kk < kk0 + 256; kk += 64) {
        __syncthreads();
        // x tile -> AsT (transposed), float4 staging
#pragma unroll
        for (int i = 0; i < 4; i++) {
            const int idx4 = t + i * 256;          // 0..1023
            const int r = idx4 >> 4, c4 = idx4 & 15;
            const float4 v = *(const float4*)(x + (size_t)(row0 + r) * Cv + kk + 4 * c4);
            AsT[(4 * c4 + 0) * LDT + r] = v.x;
            AsT[(4 * c4 + 1) * LDT + r] = v.y;
            AsT[(4 * c4 + 2) * LDT + r] = v.z;
            AsT[(4 * c4 + 3) * LDT + r] = v.w;
        }
        // Wq tile -> Bs direct, float4
#pragma unroll
        for (int i = 0; i < 4; i++) {
            const int idx4 = t + i * 256;
            const int r = idx4 >> 4, c4 = idx4 & 15;
            ((float4*)(Bs + r * 64))[c4] =
                *(const float4*)(Wq + (size_t)(kk + r) * Hv + 4 * c4);
        }
        __syncthreads();
#pragma unroll 8
        for (int k = 0; k < 64; k++) {
            const float4 a4 = *(const float4*)(AsT + k * LDT + ty * 4);
            float b[4];
#pragma unroll
            for (int j = 0; j < 4; j++) b[j] = Bs[k * 64 + tx + 16 * j];
            acc[0][0] += a4.x * b[0]; acc[0][1] += a4.x * b[1];
            acc[0][2] += a4.x * b[2]; acc[0][3] += a4.x * b[3];
            acc[1][0] += a4.y * b[0]; acc[1][1] += a4.y * b[1];
            acc[1][2] += a4.y * b[2]; acc[1][3] += a4.y * b[3];
            acc[2][0] += a4.z * b[0]; acc[2][1] += a4.z * b[1];
            acc[2][2] += a4.z * b[2]; acc[2][3] += a4.z * b[3];
            acc[3][0] += a4.w * b[0]; acc[3][1] += a4.w * b[1];
            acc[3][2] += a4.w * b[2]; acc[3][3] += a4.w * b[3];
        }
    }
#pragma unroll
    for (int i = 0; i < 4; i++)
#pragma unroll
        for (int j = 0; j < 4; j++)
            g_qp[part][(size_t)(row0 + ty * 4 + i) * Hv + tx + 16 * j] = acc[i][j];
}

// ---------------------------------------------------------------------------
// Kernel 2: reduce split-K partials.
// ---------------------------------------------------------------------------
__global__ __launch_bounds__(256) void qproj_reduce() {
    const int i = blockIdx.x * 256 + threadIdx.x;
    const float4 a = ((const float4*)g_qp[0])[i];
    const float4 b = ((const float4*)g_qp[1])[i];
    const float4 c = ((const float4*)g_qp[2])[i];
    float4 r;
    r.x = a.x + b.x + c.x;  r.y = a.y + b.y + c.y;
    r.z = a.z + b.z + c.z;  r.w = a.w + b.w + c.w;
    ((float4*)g_q)[i] = r;
}

// ---------------------------------------------------------------------------
// Kernel 3: split-KV flash attention chunk, vectorized smem GEMMs.
// ---------------------------------------------------------------------------
__global__ __launch_bounds__(256, 3) void attn_chunk(const float* __restrict__ rel) {
    extern __shared__ float smem[];
    float* QsT  = smem;                   // [64][LDT]  QsT[k*LDT + r]
    float* Ks   = QsT + 64 * LDT;         // [64][LDT]  Ks[r*LDT + k]
    float* PsT  = Ks + 64 * LDT;          // [64][LDT]  PsT[c*LDT + r]
    float* bias = PsT + 64 * LDT;         // 128

    const int qt = blockIdx.x;
    const int b  = blockIdx.y;
    const int ch = blockIdx.z;
    const int nch = (qt >> 3) + 1;
    if (ch >= nch) return;

    const int t = threadIdx.x;
    const int tx = t & 15, ty = t >> 4;
    const float* qbase = g_q + (size_t)b * Tv * Hv;

    // Q tile -> QsT (transposed), float4 staging
    {
        const float4* q4 = (const float4*)(qbase + (size_t)(qt * 64) * Hv);
#pragma unroll
        for (int i = 0; i < 4; i++) {
            const int idx4 = t + i * 256;
            const int r = idx4 >> 4, c4 = idx4 & 15;
            const float4 v = q4[idx4];
            QsT[(4 * c4 + 0) * LDT + r] = v.x;
            QsT[(4 * c4 + 1) * LDT + r] = v.y;
            QsT[(4 * c4 + 2) * LDT + r] = v.z;
            QsT[(4 * c4 + 3) * LDT + r] = v.w;
        }
    }

    float m[4], l[4], acc[4][4];
#pragma unroll
    for (int i = 0; i < 4; i++) {
        m[i] = -1e30f; l[i] = 0.f;
#pragma unroll
        for (int j = 0; j < 4; j++) acc[i][j] = 0.f;
    }

    const int kt0 = ch * CHT;
    const int kt1 = min(kt0 + CHT - 1, qt);

    for (int kt = kt0; kt <= kt1; kt++) {
        __syncthreads();
        // K tile (== V tile) -> Ks row-major, float4
        {
            const float4* k4 = (const float4*)(qbase + (size_t)(kt * 64) * Hv);
#pragma unroll
            for (int i = 0; i < 4; i++) {
                const int idx4 = t + i * 256;
                const int r = idx4 >> 4, c4 = idx4 & 15;
                ((float4*)(Ks + r * LDT))[c4] = k4[idx4];
            }
        }
        if (t < 127) bias[t] = rel[(kt - qt) * 64 - 63 + 2047 + t];
        __syncthreads();

        // ---- S = Q @ K^T (k vectorized in groups of 4) ----
        float s[4][4] = {};
#pragma unroll
        for (int kc = 0; kc < 16; kc++) {
            float4 kb4[4];
#pragma unroll
            for (int j = 0; j < 4; j++)
                kb4[j] = *(const float4*)(Ks + (tx + 16 * j) * LDT + 4 * kc);
#pragma unroll
            for (int u = 0; u < 4; u++) {
                const float4 a4 = *(const float4*)(QsT + (4 * kc + u) * LDT + ty * 4);
#pragma unroll
                for (int j = 0; j < 4; j++) {
                    const float kb = ((const float*)&kb4[j])[u];
                    s[0][j] += a4.x * kb;
                    s[1][j] += a4.y * kb;
                    s[2][j] += a4.z * kb;
                    s[3][j] += a4.w * kb;
                }
            }
        }

        // ---- scale + bias + causal + online softmax ----
        const bool diag = (kt == qt);
        float mloc[4];
#pragma unroll
        for (int i = 0; i < 4; i++) {
            const int r = ty * 4 + i;
            mloc[i] = -1e30f;
#pragma unroll
            for (int j = 0; j < 4; j++) {
                const int c = tx + 16 * j;
                float v = s[i][j] * 0.125f + bias[c - r + 63];
                if (diag && c > r) v = -1e30f;
                s[i][j] = v;
                mloc[i] = fmaxf(mloc[i], v);
            }
        }
#pragma unroll
        for (int off = 1; off < 16; off <<= 1)
#pragma unroll
            for (int i = 0; i < 4; i++)
                mloc[i] = fmaxf(mloc[i], __shfl_xor_sync(0xffffffffu, mloc[i], off));

        float rs[4];
#pragma unroll
        for (int i = 0; i < 4; i++) {
            const float mnew  = fmaxf(m[i], mloc[i]);
            const float alpha = __expf(m[i] - mnew);
            m[i] = mnew;
            float sum = 0.f;
#pragma unroll
            for (int j = 0; j < 4; j++) {
                const float p = __expf(s[i][j] - mnew);
                sum += p;
                PsT[(tx + 16 * j) * LDT + ty * 4 + i] = p;   // transposed store
            }
            rs[i] = sum;
            l[i] *= alpha;
#pragma unroll
            for (int j = 0; j < 4; j++) acc[i][j] *= alpha;
        }
#pragma unroll
        for (int off = 1; off < 16; off <<= 1)
#pragma unroll
            for (int i = 0; i < 4; i++)
                rs[i] += __shfl_xor_sync(0xffffffffu, rs[i], off);
#pragma unroll
        for (int i = 0; i < 4; i++) l[i] += rs[i];

        __syncthreads();

        // ---- O += P @ V  (V = Ks) ----
#pragma unroll 8
        for (int c = 0; c < 64; c++) {
            const float4 p4 = *(const float4*)(PsT + c * LDT + ty * 4);
            float v[4];
#pragma unroll
            for (int j = 0; j < 4; j++) v[j] = Ks[c * LDT + tx + 16 * j];
#pragma unroll
            for (int j = 0; j < 4; j++) {
                acc[0][j] += p4.x * v[j];
                acc[1][j] += p4.y * v[j];
                acc[2][j] += p4.z * v[j];
                acc[3][j] += p4.w * v[j];
            }
        }
    }

    // ---- write partials ----
    const size_t slot = ((size_t)(b * 32 + qt) * NCH + ch);
    float* pacc = g_pacc + slot * 4096;
    float* pml  = g_pml  + slot * 128;
#pragma unroll
    for (int i = 0; i < 4; i++) {
#pragma unroll
        for (int j = 0; j < 4; j++)
            pacc[(ty * 4 + i) * 64 + tx + 16 * j] = acc[i][j];
        if (tx == 0) {
            pml[(ty * 4 + i) * 2 + 0] = m[i];
            pml[(ty * 4 + i) * 2 + 1] = l[i];
        }
    }
}

// ---------------------------------------------------------------------------
// Kernel 4: combine chunk partials -> final output (float4, high MLP).
// ---------------------------------------------------------------------------
__global__ __launch_bounds__(256) void attn_combine(float* __restrict__ out) {
    __shared__ float ws[NCH][64];
    const int qt = blockIdx.x;
    const int b  = blockIdx.y;
    const int nch = (qt >> 3) + 1;
    const int t = threadIdx.x;
    const size_t base = (size_t)(b * 32 + qt) * NCH;

    if (t < 64) {
        float mm[NCH], ll[NCH];
        float M = -1e30f;
        for (int c = 0; c < nch; c++) {
            mm[c] = g_pml[(base + c) * 128 + t * 2 + 0];
            ll[c] = g_pml[(base + c) * 128 + t * 2 + 1];
            M = fmaxf(M, mm[c]);
        }
        float L = 0.f;
        for (int c = 0; c < nch; c++) L += __expf(mm[c] - M) * ll[c];
        const float inv = 1.f / L;
        for (int c = 0; c < nch; c++) ws[c][t] = __expf(mm[c] - M) * inv;
    }
    __syncthreads();

    const float4* pacc4 = (const float4*)g_pacc;
    float4* out4 = (float4*)(out + ((size_t)b * Tv + qt * 64) * Hv);
#pragma unroll
    for (int i = 0; i < 4; i++) {
        const int idx4 = t + i * 256;        // 0..1023 float4s
        const int r = idx4 >> 4;
        float4 s = make_float4(0.f, 0.f, 0.f, 0.f);
        for (int c = 0; c < nch; c++) {
            const float4 pv = pacc4[(base + c) * 1024 + idx4];
            const float w = ws[c][r];
            s.x += pv.x * w;  s.y += pv.y * w;
            s.z += pv.z * w;  s.w += pv.w * w;
        }
        out4[idx4] = s;
    }
}

// ---------------------------------------------------------------------------
extern "C" void kernel_launch(void* const* d_in, const int* in_sizes, int n_in,
                              void* d_out, int out_size) {
    const float* x   = (const float*)d_in[0];
    const float* Wq  = (const float*)d_in[1];
    const float* rel = (const float*)d_in[2];
    float* out = (float*)d_out;

    const int smem_bytes = (3 * 64 * LDT + 128) * sizeof(float);   // 52736
    cudaFuncSetAttribute(attn_chunk, cudaFuncAttributeMaxDynamicSharedMemorySize, smem_bytes);

    qproj_part<<<dim3(Bv * Tv / 64, 3), 256>>>(x, Wq);
    qproj_reduce<<<(Bv * Tv * Hv / 4) / 256, 256>>>();
    attn_chunk<<<dim3(Tv / 64, Bv, NCH), 256, smem_bytes>>>(rel);
    attn_combine<<<dim3(Tv / 64, Bv), 256>>>(out);
}

// round 6
// speedup vs baseline: 2.6759x; 1.7235x over previous
#include <cuda_runtime.h>
#include <cuda_bf16.h>
#include <cstdint>

#define Bv 8
#define Tv 2048
#define Cv 768
#define Hv 64
#define NCH 4          // max KV chunks per 128-row query block
#define LDK 72         // bf16 row stride for 64-wide tiles (144B: ldmatrix conflict-free)

// ---- scratch (__device__ globals) ----
__device__ float g_qp[3][Bv * Tv * Hv];
__device__ float g_q[Bv * Tv * Hv];
__device__ float g_pacc[Bv * 16 * NCH * 128 * 64];   // partial O per (b,qb,ch)
__device__ float g_pml[Bv * 16 * NCH * 128 * 2];     // partial (m,l)

// ============================ mma / ldmatrix helpers =========================
__device__ __forceinline__ void mma16816(float* c, const uint32_t* a, uint32_t b0, uint32_t b1) {
    asm volatile(
        "mma.sync.aligned.m16n8k16.row.col.f32.bf16.bf16.f32 "
        "{%0,%1,%2,%3}, {%4,%5,%6,%7}, {%8,%9}, {%0,%1,%2,%3};"
        : "+f"(c[0]), "+f"(c[1]), "+f"(c[2]), "+f"(c[3])
        : "r"(a[0]), "r"(a[1]), "r"(a[2]), "r"(a[3]), "r"(b0), "r"(b1));
}
__device__ __forceinline__ void ldsm4(uint32_t addr, uint32_t& r0, uint32_t& r1,
                                      uint32_t& r2, uint32_t& r3) {
    asm volatile("ldmatrix.sync.aligned.m8n8.x4.shared.b16 {%0,%1,%2,%3}, [%4];"
                 : "=r"(r0), "=r"(r1), "=r"(r2), "=r"(r3) : "r"(addr));
}
__device__ __forceinline__ void ldsm4t(uint32_t addr, uint32_t& r0, uint32_t& r1,
                                       uint32_t& r2, uint32_t& r3) {
    asm volatile("ldmatrix.sync.aligned.m8n8.x4.trans.shared.b16 {%0,%1,%2,%3}, [%4];"
                 : "=r"(r0), "=r"(r1), "=r"(r2), "=r"(r3) : "r"(addr));
}
__device__ __forceinline__ uint32_t pack_bf16(float lo, float hi) {
    __nv_bfloat162 h = __floats2bfloat162_rn(lo, hi);   // .x = lo half
    return *reinterpret_cast<uint32_t*>(&h);
}
// split float4 -> (hi uint2, lo uint2) bf16 pairs
__device__ __forceinline__ void split4(float4 v, uint2& hi, uint2& lo) {
    __nv_bfloat162 ha = __floats2bfloat162_rn(v.x, v.y);
    __nv_bfloat162 hb = __floats2bfloat162_rn(v.z, v.w);
    float lx = v.x - __bfloat162float(ha.x), ly = v.y - __bfloat162float(ha.y);
    float lz = v.z - __bfloat162float(hb.x), lw = v.w - __bfloat162float(hb.y);
    __nv_bfloat162 la = __floats2bfloat162_rn(lx, ly);
    __nv_bfloat162 lb = __floats2bfloat162_rn(lz, lw);
    hi = make_uint2(*reinterpret_cast<uint32_t*>(&ha), *reinterpret_cast<uint32_t*>(&hb));
    lo = make_uint2(*reinterpret_cast<uint32_t*>(&la), *reinterpret_cast<uint32_t*>(&lb));
}

// ---------------------------------------------------------------------------
// Kernel 1: split-K q-projection (SIMT, proven).
// ---------------------------------------------------------------------------
__global__ __launch_bounds__(256) void qproj_part(const float* __restrict__ x,
                                                  const float* __restrict__ Wq) {
    __shared__ float AsT[64 * 68];
    __shared__ float Bs[64 * 64];
    const int t = threadIdx.x;
    const int tx = t & 15, ty = t >> 4;
    const int row0 = blockIdx.x * 64;
    const int part = blockIdx.y;

    float acc[4][4] = {};
    const int kk0 = part * 256;
    for (int kk = kk0; kk < kk0 + 256; kk += 64) {
        __syncthreads();
#pragma unroll
        for (int i = 0; i < 4; i++) {
            const int idx4 = t + i * 256;
            const int r = idx4 >> 4, c4 = idx4 & 15;
            const float4 v = *(const float4*)(x + (size_t)(row0 + r) * Cv + kk + 4 * c4);
            AsT[(4 * c4 + 0) * 68 + r] = v.x;
            AsT[(4 * c4 + 1) * 68 + r] = v.y;
            AsT[(4 * c4 + 2) * 68 + r] = v.z;
            AsT[(4 * c4 + 3) * 68 + r] = v.w;
        }
#pragma unroll
        for (int i = 0; i < 4; i++) {
            const int idx4 = t + i * 256;
            const int r = idx4 >> 4, c4 = idx4 & 15;
            ((float4*)(Bs + r * 64))[c4] = *(const float4*)(Wq + (size_t)(kk + r) * Hv + 4 * c4);
        }
        __syncthreads();
#pragma unroll 8
        for (int k = 0; k < 64; k++) {
            const float4 a4 = *(const float4*)(AsT + k * 68 + ty * 4);
            float b[4];
#pragma unroll
            for (int j = 0; j < 4; j++) b[j] = Bs[k * 64 + tx + 16 * j];
            acc[0][0] += a4.x * b[0]; acc[0][1] += a4.x * b[1];
            acc[0][2] += a4.x * b[2]; acc[0][3] += a4.x * b[3];
            acc[1][0] += a4.y * b[0]; acc[1][1] += a4.y * b[1];
            acc[1][2] += a4.y * b[2]; acc[1][3] += a4.y * b[3];
            acc[2][0] += a4.z * b[0]; acc[2][1] += a4.z * b[1];
            acc[2][2] += a4.z * b[2]; acc[2][3] += a4.z * b[3];
            acc[3][0] += a4.w * b[0]; acc[3][1] += a4.w * b[1];
            acc[3][2] += a4.w * b[2]; acc[3][3] += a4.w * b[3];
        }
    }
#pragma unroll
    for (int i = 0; i < 4; i++)
#pragma unroll
        for (int j = 0; j < 4; j++)
            g_qp[part][(size_t)(row0 + ty * 4 + i) * Hv + tx + 16 * j] = acc[i][j];
}

__global__ __launch_bounds__(256) void qproj_reduce() {
    const int i = blockIdx.x * 256 + threadIdx.x;
    const float4 a = ((const float4*)g_qp[0])[i];
    const float4 b = ((const float4*)g_qp[1])[i];
    const float4 c = ((const float4*)g_qp[2])[i];
    float4 r;
    r.x = a.x + b.x + c.x;  r.y = a.y + b.y + c.y;
    r.z = a.z + b.z + c.z;  r.w = a.w + b.w + c.w;
    ((float4*)g_q)[i] = r;
}

// ---------------------------------------------------------------------------
// Kernel 3: tensor-core flash attention chunk (bf16 3-term compensated).
// CTA = 128 query rows x one KV chunk (<=8 key tiles of 64).
// Warp w owns rows w*16..w*16+15, full 64-key width -> warp-local softmax.
// ---------------------------------------------------------------------------
__global__ __launch_bounds__(256) void attn_chunk(const float* __restrict__ rel) {
    extern __shared__ char smc[];
    __nv_bfloat16* Qhi = (__nv_bfloat16*)smc;            // 128*LDK
    __nv_bfloat16* Qlo = Qhi + 128 * LDK;
    __nv_bfloat16* Khi = Qlo + 128 * LDK;                // 64*LDK
    __nv_bfloat16* Klo = Khi + 64 * LDK;
    float* bias_s = (float*)(Klo + 64 * LDK);            // 192 floats

    const int qb = blockIdx.x;       // 0..15 (128-row block)
    const int b  = blockIdx.y;
    const int ch = blockIdx.z;
    const int nkt = 2 * qb + 2;
    const int nch = (nkt + 7) >> 3;
    if (ch >= nch) return;

    const int t = threadIdx.x;
    const int w = t >> 5, l = t & 31;
    const int gid = l >> 2, tig = l & 3;
    const float* qbase = g_q + (size_t)b * Tv * Hv;

    // ---- stage Q block (128x64) as bf16 hi/lo ----
    {
        const float4* src = (const float4*)(qbase + (size_t)(qb * 128) * Hv);
#pragma unroll
        for (int i = 0; i < 8; i++) {
            const int idx4 = t + i * 256;            // 0..2047
            const int r = idx4 >> 4, c4 = idx4 & 15;
            uint2 hi, lo;
            split4(src[idx4], hi, lo);
            *(uint2*)(Qhi + r * LDK + 4 * c4) = hi;
            *(uint2*)(Qlo + r * LDK + 4 * c4) = lo;
        }
    }
    __syncthreads();

    // lane patterns for ldmatrix addressing
    const int patA_row = l & 15;
    const int patA_col = (l >> 1) & 8;         // (l&16)?8:0
    const int patB_row = (l & 7) | ((l >> 1) & 8);
    const int patB_col = l & 8;

    const uint32_t QhiB = (uint32_t)__cvta_generic_to_shared(Qhi);
    const uint32_t QloB = (uint32_t)__cvta_generic_to_shared(Qlo);
    const uint32_t KhiB = (uint32_t)__cvta_generic_to_shared(Khi);
    const uint32_t KloB = (uint32_t)__cvta_generic_to_shared(Klo);

    // ---- Q fragments (resident) ----
    uint32_t qh[4][4], ql[4][4];
#pragma unroll
    for (int ks = 0; ks < 4; ks++) {
        const uint32_t off = (uint32_t)(((w * 16 + patA_row) * LDK + ks * 16 + patA_col) * 2);
        ldsm4(QhiB + off, qh[ks][0], qh[ks][1], qh[ks][2], qh[ks][3]);
        ldsm4(QloB + off, ql[ks][0], ql[ks][1], ql[ks][2], ql[ks][3]);
    }

    float o[8][4];
#pragma unroll
    for (int nb = 0; nb < 8; nb++)
#pragma unroll
        for (int c = 0; c < 4; c++) o[nb][c] = 0.f;
    float m0 = -1e30f, m1 = -1e30f, l0 = 0.f, l1 = 0.f;

    const int rl0 = w * 16 + gid, rl1 = rl0 + 8;       // local rows
    const int qrow0 = qb * 128 + rl0;                  // absolute rows
    const int kt0 = ch * 8;
    const int kt1 = min(kt0 + 7, nkt - 1);

    for (int kt = kt0; kt <= kt1; kt++) {
        __syncthreads();
        // load K tile (== V), split hi/lo
        {
            const float4* src = (const float4*)(qbase + (size_t)(kt * 64) * Hv);
#pragma unroll
            for (int i = 0; i < 4; i++) {
                const int idx4 = t + i * 256;        // 0..1023
                const int r = idx4 >> 4, c4 = idx4 & 15;
                uint2 hi, lo;
                split4(src[idx4], hi, lo);
                *(uint2*)(Khi + r * LDK + 4 * c4) = hi;
                *(uint2*)(Klo + r * LDK + 4 * c4) = lo;
            }
        }
        if (t < 192) bias_s[t] = rel[kt * 64 - qb * 128 + 1920 + t];
        __syncthreads();

        // ---- S = Q @ K^T  (3-term compensated) ----
        float sc[8][4];
#pragma unroll
        for (int nb = 0; nb < 8; nb++)
#pragma unroll
            for (int c = 0; c < 4; c++) sc[nb][c] = 0.f;

#pragma unroll
        for (int ks = 0; ks < 4; ks++) {
#pragma unroll
            for (int nb2 = 0; nb2 < 4; nb2++) {
                const uint32_t off =
                    (uint32_t)((((nb2 * 16) + patB_row) * LDK + ks * 16 + patB_col) * 2);
                uint32_t bh0, bh1, bh2, bh3, bl0, bl1, bl2, bl3;
                ldsm4(KhiB + off, bh0, bh1, bh2, bh3);
                ldsm4(KloB + off, bl0, bl1, bl2, bl3);
                mma16816(sc[2 * nb2],     qh[ks], bh0, bh1);
                mma16816(sc[2 * nb2],     qh[ks], bl0, bl1);
                mma16816(sc[2 * nb2],     ql[ks], bh0, bh1);
                mma16816(sc[2 * nb2 + 1], qh[ks], bh2, bh3);
                mma16816(sc[2 * nb2 + 1], qh[ks], bl2, bl3);
                mma16816(sc[2 * nb2 + 1], ql[ks], bh2, bh3);
            }
        }

        // ---- softmax (warp-local; rows owned by 4-lane quads) ----
        float mx0 = -1e30f, mx1 = -1e30f;
#pragma unroll
        for (int nb = 0; nb < 8; nb++) {
            const int kl = nb * 8 + 2 * tig;
            const int key = kt * 64 + kl;
            float v0 = sc[nb][0] * 0.125f + bias_s[kl - rl0 + 127];
            float v1 = sc[nb][1] * 0.125f + bias_s[kl + 1 - rl0 + 127];
            float v2 = sc[nb][2] * 0.125f + bias_s[kl - rl1 + 127];
            float v3 = sc[nb][3] * 0.125f + bias_s[kl + 1 - rl1 + 127];
            if (key > qrow0)         v0 = -1e30f;
            if (key + 1 > qrow0)     v1 = -1e30f;
            if (key > qrow0 + 8)     v2 = -1e30f;
            if (key + 1 > qrow0 + 8) v3 = -1e30f;
            sc[nb][0] = v0; sc[nb][1] = v1; sc[nb][2] = v2; sc[nb][3] = v3;
            mx0 = fmaxf(mx0, fmaxf(v0, v1));
            mx1 = fmaxf(mx1, fmaxf(v2, v3));
        }
        mx0 = fmaxf(mx0, __shfl_xor_sync(0xffffffffu, mx0, 1));
        mx0 = fmaxf(mx0, __shfl_xor_sync(0xffffffffu, mx0, 2));
        mx1 = fmaxf(mx1, __shfl_xor_sync(0xffffffffu, mx1, 1));
        mx1 = fmaxf(mx1, __shfl_xor_sync(0xffffffffu, mx1, 2));

        const float mn0 = fmaxf(m0, mx0), mn1 = fmaxf(m1, mx1);
        const float al0 = __expf(m0 - mn0), al1 = __expf(m1 - mn1);
        m0 = mn0; m1 = mn1;

        float s0 = 0.f, s1 = 0.f;
#pragma unroll
        for (int nb = 0; nb < 8; nb++) {
            sc[nb][0] = __expf(sc[nb][0] - mn0);
            sc[nb][1] = __expf(sc[nb][1] - mn0);
            sc[nb][2] = __expf(sc[nb][2] - mn1);
            sc[nb][3] = __expf(sc[nb][3] - mn1);
            s0 += sc[nb][0] + sc[nb][1];
            s1 += sc[nb][2] + sc[nb][3];
        }
        s0 += __shfl_xor_sync(0xffffffffu, s0, 1);
        s0 += __shfl_xor_sync(0xffffffffu, s0, 2);
        s1 += __shfl_xor_sync(0xffffffffu, s1, 1);
        s1 += __shfl_xor_sync(0xffffffffu, s1, 2);
        l0 = l0 * al0 + s0;
        l1 = l1 * al1 + s1;
#pragma unroll
        for (int nb = 0; nb < 8; nb++) {
            o[nb][0] *= al0; o[nb][1] *= al0;
            o[nb][2] *= al1; o[nb][3] *= al1;
        }

        // ---- repack P (accumulator layout -> A-operand layout), hi/lo ----
        uint32_t pah[4][4], pal[4][4];
#pragma unroll
        for (int ks = 0; ks < 4; ks++) {
            const float* pa = sc[2 * ks];
            const float* pb = sc[2 * ks + 1];
            pah[ks][0] = pack_bf16(pa[0], pa[1]);
            pah[ks][1] = pack_bf16(pa[2], pa[3]);
            pah[ks][2] = pack_bf16(pb[0], pb[1]);
            pah[ks][3] = pack_bf16(pb[2], pb[3]);
            __nv_bfloat162 h;
            h = *reinterpret_cast<__nv_bfloat162*>(&pah[ks][0]);
            pal[ks][0] = pack_bf16(pa[0] - __bfloat162float(h.x), pa[1] - __bfloat162float(h.y));
            h = *reinterpret_cast<__nv_bfloat162*>(&pah[ks][1]);
            pal[ks][1] = pack_bf16(pa[2] - __bfloat162float(h.x), pa[3] - __bfloat162float(h.y));
            h = *reinterpret_cast<__nv_bfloat162*>(&pah[ks][2]);
            pal[ks][2] = pack_bf16(pb[0] - __bfloat162float(h.x), pb[1] - __bfloat162float(h.y));
            h = *reinterpret_cast<__nv_bfloat162*>(&pah[ks][3]);
            pal[ks][3] = pack_bf16(pb[2] - __bfloat162float(h.x), pb[3] - __bfloat162float(h.y));
        }

        // ---- O += P @ V  (V = K tile; 3-term compensated) ----
#pragma unroll
        for (int ks = 0; ks < 4; ks++) {
#pragma unroll
            for (int nb2 = 0; nb2 < 4; nb2++) {
                const uint32_t off =
                    (uint32_t)(((ks * 16 + patA_row) * LDK + nb2 * 16 + patA_col) * 2);
                uint32_t vh0, vh1, vh2, vh3, vl0, vl1, vl2, vl3;
                ldsm4t(KhiB + off, vh0, vh1, vh2, vh3);
                ldsm4t(KloB + off, vl0, vl1, vl2, vl3);
                mma16816(o[2 * nb2],     pah[ks], vh0, vh1);
                mma16816(o[2 * nb2],     pah[ks], vl0, vl1);
                mma16816(o[2 * nb2],     pal[ks], vh0, vh1);
                mma16816(o[2 * nb2 + 1], pah[ks], vh2, vh3);
                mma16816(o[2 * nb2 + 1], pah[ks], vl2, vl3);
                mma16816(o[2 * nb2 + 1], pal[ks], vh2, vh3);
            }
        }
    }

    // ---- write partials ----
    const size_t slot = ((size_t)(b * 16 + qb) * NCH + ch);
    float* pacc = g_pacc + slot * (128 * 64);
#pragma unroll
    for (int nb = 0; nb < 8; nb++) {
        const int col = nb * 8 + 2 * tig;
        *(float2*)&pacc[rl0 * 64 + col] = make_float2(o[nb][0], o[nb][1]);
        *(float2*)&pacc[rl1 * 64 + col] = make_float2(o[nb][2], o[nb][3]);
    }
    if (tig == 0) {
        float* pml = g_pml + slot * 256;
        pml[rl0 * 2 + 0] = m0;  pml[rl0 * 2 + 1] = l0;
        pml[rl1 * 2 + 0] = m1;  pml[rl1 * 2 + 1] = l1;
    }
}

// ---------------------------------------------------------------------------
// Kernel 4: combine chunk partials -> final output.
// ---------------------------------------------------------------------------
__global__ __launch_bounds__(256) void attn_combine(float* __restrict__ out) {
    __shared__ float ws[NCH][128];
    const int qb = blockIdx.x;
    const int b  = blockIdx.y;
    const int nch = (2 * qb + 9) >> 3;       // ceil((2qb+2)/8)
    const int t = threadIdx.x;
    const size_t base = (size_t)(b * 16 + qb) * NCH;

    if (t < 128) {
        float mm[NCH], ll[NCH];
        float M = -1e30f;
        for (int c = 0; c < nch; c++) {
            mm[c] = g_pml[(base + c) * 256 + t * 2 + 0];
            ll[c] = g_pml[(base + c) * 256 + t * 2 + 1];
            M = fmaxf(M, mm[c]);
        }
        float L = 0.f;
        for (int c = 0; c < nch; c++) L += __expf(mm[c] - M) * ll[c];
        const float inv = 1.f / L;
        for (int c = 0; c < nch; c++) ws[c][t] = __expf(mm[c] - M) * inv;
    }
    __syncthreads();

    const float4* pacc4 = (const float4*)g_pacc;
    float4* out4 = (float4*)(out + ((size_t)b * Tv + qb * 128) * Hv);
#pragma unroll
    for (int i = 0; i < 8; i++) {
        const int idx4 = t + i * 256;            // 0..2047 float4s
        const int r = idx4 >> 4;
        float4 s = make_float4(0.f, 0.f, 0.f, 0.f);
        for (int c = 0; c < nch; c++) {
            const float4 pv = pacc4[(base + c) * 2048 + idx4];
            const float w = ws[c][r];
            s.x += pv.x * w;  s.y += pv.y * w;
            s.z += pv.z * w;  s.w += pv.w * w;
        }
        out4[idx4] = s;
    }
}

// ---------------------------------------------------------------------------
extern "C" void kernel_launch(void* const* d_in, const int* in_sizes, int n_in,
                              void* d_out, int out_size) {
    const float* x   = (const float*)d_in[0];
    const float* Wq  = (const float*)d_in[1];
    const float* rel = (const float*)d_in[2];
    float* out = (float*)d_out;

    const int smem_bytes = (2 * 128 * LDK + 2 * 64 * LDK) * 2 + 192 * 4;  // 56064
    cudaFuncSetAttribute(attn_chunk, cudaFuncAttributeMaxDynamicSharedMemorySize, smem_bytes);

    qproj_part<<<dim3(Bv * Tv / 64, 3), 256>>>(x, Wq);
    qproj_reduce<<<(Bv * Tv * Hv / 4) / 256, 256>>>();
    attn_chunk<<<dim3(16, Bv, NCH), 256, smem_bytes>>>(rel);
    attn_combine<<<dim3(16, Bv), 256>>>(out);
}

// round 7
// speedup vs baseline: 4.0883x; 1.5278x over previous
#include <cuda_runtime.h>
#include <cuda_bf16.h>
#include <cstdint>

#define Bv 8
#define Tv 2048
#define Cv 768
#define Hv 64
#define NCH 4
#define LDK 72       // bf16 row stride (144B) for 64-wide tiles: ldmatrix conflict-free

// ---- scratch (__device__ globals) ----
__device__ __nv_bfloat16 g_qh[Bv * Tv * Hv];         // q hi plane (bf16)
__device__ __nv_bfloat16 g_ql[Bv * Tv * Hv];         // q lo plane (bf16)
__device__ float g_pacc[Bv * 16 * NCH * 128 * 64];   // partial O
__device__ float g_pml[Bv * 16 * NCH * 128 * 2];     // partial (m,l)

// ============================ helpers =========================
__device__ __forceinline__ void mma16816(float* c, const uint32_t* a, uint32_t b0, uint32_t b1) {
    asm volatile(
        "mma.sync.aligned.m16n8k16.row.col.f32.bf16.bf16.f32 "
        "{%0,%1,%2,%3}, {%4,%5,%6,%7}, {%8,%9}, {%0,%1,%2,%3};"
        : "+f"(c[0]), "+f"(c[1]), "+f"(c[2]), "+f"(c[3])
        : "r"(a[0]), "r"(a[1]), "r"(a[2]), "r"(a[3]), "r"(b0), "r"(b1));
}
__device__ __forceinline__ void ldsm4(uint32_t addr, uint32_t& r0, uint32_t& r1,
                                      uint32_t& r2, uint32_t& r3) {
    asm volatile("ldmatrix.sync.aligned.m8n8.x4.shared.b16 {%0,%1,%2,%3}, [%4];"
                 : "=r"(r0), "=r"(r1), "=r"(r2), "=r"(r3) : "r"(addr));
}
__device__ __forceinline__ void ldsm4t(uint32_t addr, uint32_t& r0, uint32_t& r1,
                                       uint32_t& r2, uint32_t& r3) {
    asm volatile("ldmatrix.sync.aligned.m8n8.x4.trans.shared.b16 {%0,%1,%2,%3}, [%4];"
                 : "=r"(r0), "=r"(r1), "=r"(r2), "=r"(r3) : "r"(addr));
}
__device__ __forceinline__ uint32_t pack_bf16(float lo, float hi) {
    __nv_bfloat162 h = __floats2bfloat162_rn(lo, hi);
    return *reinterpret_cast<uint32_t*>(&h);
}
__device__ __forceinline__ void split4(float4 v, uint2& hi, uint2& lo) {
    __nv_bfloat162 ha = __floats2bfloat162_rn(v.x, v.y);
    __nv_bfloat162 hb = __floats2bfloat162_rn(v.z, v.w);
    __nv_bfloat162 la = __floats2bfloat162_rn(v.x - __bfloat162float(ha.x),
                                              v.y - __bfloat162float(ha.y));
    __nv_bfloat162 lb = __floats2bfloat162_rn(v.z - __bfloat162float(hb.x),
                                              v.w - __bfloat162float(hb.y));
    hi = make_uint2(*reinterpret_cast<uint32_t*>(&ha), *reinterpret_cast<uint32_t*>(&hb));
    lo = make_uint2(*reinterpret_cast<uint32_t*>(&la), *reinterpret_cast<uint32_t*>(&lb));
}
__device__ __forceinline__ void cpa16(uint32_t dst, const void* src) {
    asm volatile("cp.async.ca.shared.global [%0], [%1], 16;" :: "r"(dst), "l"(src));
}

// ---------------------------------------------------------------------------
// Kernel 1: tensor-core q-projection -> bf16 hi/lo planes.
// CTA = 128 rows of flattened [B*T]. 8 warps x m16. K = 768 in 64-chunks,
// register-prefetch double buffering of x and Wq tiles.
// ---------------------------------------------------------------------------
__global__ __launch_bounds__(256) void qproj_tc(const float* __restrict__ x,
                                                const float* __restrict__ Wq) {
    extern __shared__ char smc[];
    __nv_bfloat16* Xhi = (__nv_bfloat16*)smc;            // 128*LDK
    __nv_bfloat16* Xlo = Xhi + 128 * LDK;
    __nv_bfloat16* Whi = Xlo + 128 * LDK;                // 64*LDK
    __nv_bfloat16* Wlo = Whi + 64 * LDK;

    const int t = threadIdx.x;
    const int w = t >> 5, l = t & 31;
    const int gid = l >> 2, tig = l & 3;
    const int row0 = blockIdx.x * 128;

    const int patA_row = l & 15;
    const int patA_col = (l >> 1) & 8;

    const uint32_t XhiB = (uint32_t)__cvta_generic_to_shared(Xhi);
    const uint32_t XloB = (uint32_t)__cvta_generic_to_shared(Xlo);
    const uint32_t WhiB = (uint32_t)__cvta_generic_to_shared(Whi);
    const uint32_t WloB = (uint32_t)__cvta_generic_to_shared(Wlo);

    float o[8][4];
#pragma unroll
    for (int nb = 0; nb < 8; nb++)
#pragma unroll
        for (int c = 0; c < 4; c++) o[nb][c] = 0.f;

    // prefetch first tiles into registers
    float4 px[8], pw[4];
#pragma unroll
    for (int i = 0; i < 8; i++) {
        const int idx4 = t + i * 256;
        const int r = idx4 >> 4, c4 = idx4 & 15;
        px[i] = *(const float4*)(x + (size_t)(row0 + r) * Cv + 4 * c4);
    }
#pragma unroll
    for (int i = 0; i < 4; i++) {
        const int idx4 = t + i * 256;
        const int r = idx4 >> 4, c4 = idx4 & 15;
        pw[i] = *(const float4*)(Wq + (size_t)r * Hv + 4 * c4);
    }

    for (int kk = 0; kk < Cv; kk += 64) {
        __syncthreads();
        // store staged tiles (split hi/lo)
#pragma unroll
        for (int i = 0; i < 8; i++) {
            const int idx4 = t + i * 256;
            const int r = idx4 >> 4, c4 = idx4 & 15;
            uint2 hi, lo;
            split4(px[i], hi, lo);
            *(uint2*)(Xhi + r * LDK + 4 * c4) = hi;
            *(uint2*)(Xlo + r * LDK + 4 * c4) = lo;
        }
#pragma unroll
        for (int i = 0; i < 4; i++) {
            const int idx4 = t + i * 256;
            const int r = idx4 >> 4, c4 = idx4 & 15;
            uint2 hi, lo;
            split4(pw[i], hi, lo);
            *(uint2*)(Whi + r * LDK + 4 * c4) = hi;
            *(uint2*)(Wlo + r * LDK + 4 * c4) = lo;
        }
        // prefetch next tiles
        if (kk + 64 < Cv) {
#pragma unroll
            for (int i = 0; i < 8; i++) {
                const int idx4 = t + i * 256;
                const int r = idx4 >> 4, c4 = idx4 & 15;
                px[i] = *(const float4*)(x + (size_t)(row0 + r) * Cv + kk + 64 + 4 * c4);
            }
#pragma unroll
            for (int i = 0; i < 4; i++) {
                const int idx4 = t + i * 256;
                const int r = idx4 >> 4, c4 = idx4 & 15;
                pw[i] = *(const float4*)(Wq + (size_t)(kk + 64 + r) * Hv + 4 * c4);
            }
        }
        __syncthreads();

        // A fragments (x rows)
        uint32_t ah[4][4], al[4][4];
#pragma unroll
        for (int ks = 0; ks < 4; ks++) {
            const uint32_t off = (uint32_t)(((w * 16 + patA_row) * LDK + ks * 16 + patA_col) * 2);
            ldsm4(XhiB + off, ah[ks][0], ah[ks][1], ah[ks][2], ah[ks][3]);
            ldsm4(XloB + off, al[ks][0], al[ks][1], al[ks][2], al[ks][3]);
        }
        // B from Wq[k][n] row-major -> ldsm4t (PV pattern), 3-term mma
#pragma unroll
        for (int ks = 0; ks < 4; ks++) {
#pragma unroll
            for (int nb2 = 0; nb2 < 4; nb2++) {
                const uint32_t off =
                    (uint32_t)(((ks * 16 + patA_row) * LDK + nb2 * 16 + patA_col) * 2);
                uint32_t vh0, vh1, vh2, vh3, vl0, vl1, vl2, vl3;
                ldsm4t(WhiB + off, vh0, vh1, vh2, vh3);
                ldsm4t(WloB + off, vl0, vl1, vl2, vl3);
                mma16816(o[2 * nb2],     ah[ks], vh0, vh1);
                mma16816(o[2 * nb2],     ah[ks], vl0, vl1);
                mma16816(o[2 * nb2],     al[ks], vh0, vh1);
                mma16816(o[2 * nb2 + 1], ah[ks], vh2, vh3);
                mma16816(o[2 * nb2 + 1], ah[ks], vl2, vl3);
                mma16816(o[2 * nb2 + 1], al[ks], vh2, vh3);
            }
        }
    }

    // epilogue: store q as bf16 hi/lo planes
    const int rl0 = w * 16 + gid, rl1 = rl0 + 8;
#pragma unroll
    for (int nb = 0; nb < 8; nb++) {
        const int col = nb * 8 + 2 * tig;
        {
            const float a0 = o[nb][0], a1 = o[nb][1];
            const uint32_t hb = pack_bf16(a0, a1);
            const __nv_bfloat162 h = *reinterpret_cast<const __nv_bfloat162*>(&hb);
            const uint32_t lb = pack_bf16(a0 - __bfloat162float(h.x), a1 - __bfloat162float(h.y));
            *(uint32_t*)&g_qh[(size_t)(row0 + rl0) * Hv + col] = hb;
            *(uint32_t*)&g_ql[(size_t)(row0 + rl0) * Hv + col] = lb;
        }
        {
            const float a0 = o[nb][2], a1 = o[nb][3];
            const uint32_t hb = pack_bf16(a0, a1);
            const __nv_bfloat162 h = *reinterpret_cast<const __nv_bfloat162*>(&hb);
            const uint32_t lb = pack_bf16(a0 - __bfloat162float(h.x), a1 - __bfloat162float(h.y));
            *(uint32_t*)&g_qh[(size_t)(row0 + rl1) * Hv + col] = hb;
            *(uint32_t*)&g_ql[(size_t)(row0 + rl1) * Hv + col] = lb;
        }
    }
}

// ---------------------------------------------------------------------------
// Kernel 2: tensor-core flash attention chunk, cp.async double-buffered K.
// ---------------------------------------------------------------------------
__global__ __launch_bounds__(256) void attn_chunk(const float* __restrict__ rel) {
    extern __shared__ char smc[];
    __nv_bfloat16* Qhi = (__nv_bfloat16*)smc;                 // 128*LDK
    __nv_bfloat16* Qlo = Qhi + 128 * LDK;
    __nv_bfloat16* Kbuf = Qlo + 128 * LDK;                    // 2 x (Khi 64*LDK + Klo 64*LDK)
    float* bias_s = (float*)(Kbuf + 2 * 2 * 64 * LDK);        // 192 floats

    const int qb = blockIdx.x;
    const int b  = blockIdx.y;
    const int ch = blockIdx.z;
    const int nkt = 2 * qb + 2;
    const int nch = (nkt + 7) >> 3;
    if (ch >= nch) return;

    const int t = threadIdx.x;
    const int w = t >> 5, l = t & 31;
    const int gid = l >> 2, tig = l & 3;
    const __nv_bfloat16* qh_base = g_qh + (size_t)b * Tv * Hv;
    const __nv_bfloat16* ql_base = g_ql + (size_t)b * Tv * Hv;

    // ---- stage Q block (128x64 bf16 hi/lo) ----
#pragma unroll
    for (int i = 0; i < 4; i++) {
        const int idx = t + i * 256;           // 0..1023
        const int r = idx >> 3, c8 = idx & 7;
        *(uint4*)(Qhi + r * LDK + c8 * 8) =
            *(const uint4*)(qh_base + (size_t)(qb * 128 + r) * Hv + c8 * 8);
        *(uint4*)(Qlo + r * LDK + c8 * 8) =
            *(const uint4*)(ql_base + (size_t)(qb * 128 + r) * Hv + c8 * 8);
    }
    __syncthreads();

    const int patA_row = l & 15;
    const int patA_col = (l >> 1) & 8;
    const int patB_row = (l & 7) | ((l >> 1) & 8);
    const int patB_col = l & 8;

    const uint32_t QhiB = (uint32_t)__cvta_generic_to_shared(Qhi);
    const uint32_t QloB = (uint32_t)__cvta_generic_to_shared(Qlo);
    const uint32_t KB   = (uint32_t)__cvta_generic_to_shared(Kbuf);
    const uint32_t KBLK = (uint32_t)(2 * 64 * LDK * 2);   // bytes per buffer (hi+lo)
    const uint32_t KLO  = (uint32_t)(64 * LDK * 2);       // lo offset within buffer

    // ---- Q fragments (resident) ----
    uint32_t qh[4][4], ql[4][4];
#pragma unroll
    for (int ks = 0; ks < 4; ks++) {
        const uint32_t off = (uint32_t)(((w * 16 + patA_row) * LDK + ks * 16 + patA_col) * 2);
        ldsm4(QhiB + off, qh[ks][0], qh[ks][1], qh[ks][2], qh[ks][3]);
        ldsm4(QloB + off, ql[ks][0], ql[ks][1], ql[ks][2], ql[ks][3]);
    }

    float o[8][4];
#pragma unroll
    for (int nb = 0; nb < 8; nb++)
#pragma unroll
        for (int c = 0; c < 4; c++) o[nb][c] = 0.f;
    float m0 = -1e30f, m1 = -1e30f, l0 = 0.f, l1 = 0.f;

    const int rl0 = w * 16 + gid, rl1 = rl0 + 8;
    const int qrow0 = qb * 128 + rl0;
    const int kt0 = ch * 8;
    const int kt1 = min(kt0 + 7, nkt - 1);

    // issue K tile load (bf16 hi/lo, cp.async 16B)
    auto issue_k = [&](int kt, int buf) {
        const __nv_bfloat16* sh = qh_base + (size_t)(kt * 64) * Hv;
        const __nv_bfloat16* sl = ql_base + (size_t)(kt * 64) * Hv;
        const uint32_t dh = KB + (uint32_t)buf * KBLK;
#pragma unroll
        for (int i = 0; i < 2; i++) {
            const int idx = t + i * 256;       // 0..511
            const int r = idx >> 3, c8 = idx & 7;
            const uint32_t so = (uint32_t)((r * LDK + c8 * 8) * 2);
            cpa16(dh + so,       sh + r * Hv + c8 * 8);
            cpa16(dh + KLO + so, sl + r * Hv + c8 * 8);
        }
        asm volatile("cp.async.commit_group;");
    };

    issue_k(kt0, 0);

    for (int kt = kt0; kt <= kt1; kt++) {
        const int buf = (kt - kt0) & 1;
        __syncthreads();   // prev compute done (protects bias + buf^1)
        if (t < 192) bias_s[t] = rel[kt * 64 - qb * 128 + 1920 + t];
        if (kt < kt1) {
            issue_k(kt + 1, buf ^ 1);
            asm volatile("cp.async.wait_group 1;");
        } else {
            asm volatile("cp.async.wait_group 0;");
        }
        __syncthreads();   // K buf + bias visible

        const uint32_t KhiC = KB + (uint32_t)buf * KBLK;
        const uint32_t KloC = KhiC + KLO;

        // ---- S = Q @ K^T (3-term) ----
        float sc[8][4];
#pragma unroll
        for (int nb = 0; nb < 8; nb++)
#pragma unroll
            for (int c = 0; c < 4; c++) sc[nb][c] = 0.f;

#pragma unroll
        for (int ks = 0; ks < 4; ks++) {
#pragma unroll
            for (int nb2 = 0; nb2 < 4; nb2++) {
                const uint32_t off =
                    (uint32_t)((((nb2 * 16) + patB_row) * LDK + ks * 16 + patB_col) * 2);
                uint32_t bh0, bh1, bh2, bh3, bl0, bl1, bl2, bl3;
                ldsm4(KhiC + off, bh0, bh1, bh2, bh3);
                ldsm4(KloC + off, bl0, bl1, bl2, bl3);
                mma16816(sc[2 * nb2],     qh[ks], bh0, bh1);
                mma16816(sc[2 * nb2],     qh[ks], bl0, bl1);
                mma16816(sc[2 * nb2],     ql[ks], bh0, bh1);
                mma16816(sc[2 * nb2 + 1], qh[ks], bh2, bh3);
                mma16816(sc[2 * nb2 + 1], qh[ks], bl2, bl3);
                mma16816(sc[2 * nb2 + 1], ql[ks], bh2, bh3);
            }
        }

        // ---- softmax (warp-local) ----
        float mx0 = -1e30f, mx1 = -1e30f;
#pragma unroll
        for (int nb = 0; nb < 8; nb++) {
            const int kl = nb * 8 + 2 * tig;
            const int key = kt * 64 + kl;
            float v0 = sc[nb][0] * 0.125f + bias_s[kl - rl0 + 127];
            float v1 = sc[nb][1] * 0.125f + bias_s[kl + 1 - rl0 + 127];
            float v2 = sc[nb][2] * 0.125f + bias_s[kl - rl1 + 127];
            float v3 = sc[nb][3] * 0.125f + bias_s[kl + 1 - rl1 + 127];
            if (key > qrow0)         v0 = -1e30f;
            if (key + 1 > qrow0)     v1 = -1e30f;
            if (key > qrow0 + 8)     v2 = -1e30f;
            if (key + 1 > qrow0 + 8) v3 = -1e30f;
            sc[nb][0] = v0; sc[nb][1] = v1; sc[nb][2] = v2; sc[nb][3] = v3;
            mx0 = fmaxf(mx0, fmaxf(v0, v1));
            mx1 = fmaxf(mx1, fmaxf(v2, v3));
        }
        mx0 = fmaxf(mx0, __shfl_xor_sync(0xffffffffu, mx0, 1));
        mx0 = fmaxf(mx0, __shfl_xor_sync(0xffffffffu, mx0, 2));
        mx1 = fmaxf(mx1, __shfl_xor_sync(0xffffffffu, mx1, 1));
        mx1 = fmaxf(mx1, __shfl_xor_sync(0xffffffffu, mx1, 2));

        const float mn0 = fmaxf(m0, mx0), mn1 = fmaxf(m1, mx1);
        const float al0 = __expf(m0 - mn0), al1 = __expf(m1 - mn1);
        m0 = mn0; m1 = mn1;

        float s0 = 0.f, s1 = 0.f;
#pragma unroll
        for (int nb = 0; nb < 8; nb++) {
            sc[nb][0] = __expf(sc[nb][0] - mn0);
            sc[nb][1] = __expf(sc[nb][1] - mn0);
            sc[nb][2] = __expf(sc[nb][2] - mn1);
            sc[nb][3] = __expf(sc[nb][3] - mn1);
            s0 += sc[nb][0] + sc[nb][1];
            s1 += sc[nb][2] + sc[nb][3];
        }
        s0 += __shfl_xor_sync(0xffffffffu, s0, 1);
        s0 += __shfl_xor_sync(0xffffffffu, s0, 2);
        s1 += __shfl_xor_sync(0xffffffffu, s1, 1);
        s1 += __shfl_xor_sync(0xffffffffu, s1, 2);
        l0 = l0 * al0 + s0;
        l1 = l1 * al1 + s1;
#pragma unroll
        for (int nb = 0; nb < 8; nb++) {
            o[nb][0] *= al0; o[nb][1] *= al0;
            o[nb][2] *= al1; o[nb][3] *= al1;
        }

        // ---- repack P -> A-operand fragments (hi/lo) ----
        uint32_t pah[4][4], pal[4][4];
#pragma unroll
        for (int ks = 0; ks < 4; ks++) {
            const float* pa = sc[2 * ks];
            const float* pb = sc[2 * ks + 1];
            pah[ks][0] = pack_bf16(pa[0], pa[1]);
            pah[ks][1] = pack_bf16(pa[2], pa[3]);
            pah[ks][2] = pack_bf16(pb[0], pb[1]);
            pah[ks][3] = pack_bf16(pb[2], pb[3]);
            __nv_bfloat162 h;
            h = *reinterpret_cast<__nv_bfloat162*>(&pah[ks][0]);
            pal[ks][0] = pack_bf16(pa[0] - __bfloat162float(h.x), pa[1] - __bfloat162float(h.y));
            h = *reinterpret_cast<__nv_bfloat162*>(&pah[ks][1]);
            pal[ks][1] = pack_bf16(pa[2] - __bfloat162float(h.x), pa[3] - __bfloat162float(h.y));
            h = *reinterpret_cast<__nv_bfloat162*>(&pah[ks][2]);
            pal[ks][2] = pack_bf16(pb[0] - __bfloat162float(h.x), pb[1] - __bfloat162float(h.y));
            h = *reinterpret_cast<__nv_bfloat162*>(&pah[ks][3]);
            pal[ks][3] = pack_bf16(pb[2] - __bfloat162float(h.x), pb[3] - __bfloat162float(h.y));
        }

        // ---- O += P @ V (V = K tile, 3-term) ----
#pragma unroll
        for (int ks = 0; ks < 4; ks++) {
#pragma unroll
            for (int nb2 = 0; nb2 < 4; nb2++) {
                const uint32_t off =
                    (uint32_t)(((ks * 16 + patA_row) * LDK + nb2 * 16 + patA_col) * 2);
                uint32_t vh0, vh1, vh2, vh3, vl0, vl1, vl2, vl3;
                ldsm4t(KhiC + off, vh0, vh1, vh2, vh3);
                ldsm4t(KloC + off, vl0, vl1, vl2, vl3);
                mma16816(o[2 * nb2],     pah[ks], vh0, vh1);
                mma16816(o[2 * nb2],     pah[ks], vl0, vl1);
                mma16816(o[2 * nb2],     pal[ks], vh0, vh1);
                mma16816(o[2 * nb2 + 1], pah[ks], vh2, vh3);
                mma16816(o[2 * nb2 + 1], pah[ks], vl2, vl3);
                mma16816(o[2 * nb2 + 1], pal[ks], vh2, vh3);
            }
        }
    }

    // ---- write partials ----
    const size_t slot = ((size_t)(b * 16 + qb) * NCH + ch);
    float* pacc = g_pacc + slot * (128 * 64);
#pragma unroll
    for (int nb = 0; nb < 8; nb++) {
        const int col = nb * 8 + 2 * tig;
        *(float2*)&pacc[rl0 * 64 + col] = make_float2(o[nb][0], o[nb][1]);
        *(float2*)&pacc[rl1 * 64 + col] = make_float2(o[nb][2], o[nb][3]);
    }
    if (tig == 0) {
        float* pml = g_pml + slot * 256;
        pml[rl0 * 2 + 0] = m0;  pml[rl0 * 2 + 1] = l0;
        pml[rl1 * 2 + 0] = m1;  pml[rl1 * 2 + 1] = l1;
    }
}

// ---------------------------------------------------------------------------
// Kernel 3: combine chunk partials -> final output (grid.z-split for occupancy).
// ---------------------------------------------------------------------------
__global__ __launch_bounds__(256) void attn_combine(float* __restrict__ out) {
    __shared__ float ws[NCH][128];
    const int qb = blockIdx.x;
    const int b  = blockIdx.y;
    const int nch = (2 * qb + 9) >> 3;
    const int t = threadIdx.x;
    const size_t base = (size_t)(b * 16 + qb) * NCH;

    if (t < 128) {
        float mm[NCH], ll[NCH];
        float M = -1e30f;
        for (int c = 0; c < nch; c++) {
            mm[c] = g_pml[(base + c) * 256 + t * 2 + 0];
            ll[c] = g_pml[(base + c) * 256 + t * 2 + 1];
            M = fmaxf(M, mm[c]);
        }
        float L = 0.f;
        for (int c = 0; c < nch; c++) L += __expf(mm[c] - M) * ll[c];
        const float inv = 1.f / L;
        for (int c = 0; c < nch; c++) ws[c][t] = __expf(mm[c] - M) * inv;
    }
    __syncthreads();

    const float4* pacc4 = (const float4*)g_pacc;
    float4* out4 = (float4*)(out + ((size_t)b * Tv + qb * 128) * Hv);
    const int idx4 = blockIdx.z * 256 + t;       // 0..2047
    const int r = idx4 >> 4;
    float4 s = make_float4(0.f, 0.f, 0.f, 0.f);
    for (int c = 0; c < nch; c++) {
        const float4 pv = pacc4[(base + c) * 2048 + idx4];
        const float wgt = ws[c][r];
        s.x += pv.x * wgt;  s.y += pv.y * wgt;
        s.z += pv.z * wgt;  s.w += pv.w * wgt;
    }
    out4[idx4] = s;
}

// ---------------------------------------------------------------------------
extern "C" void kernel_launch(void* const* d_in, const int* in_sizes, int n_in,
                              void* d_out, int out_size) {
    const float* x   = (const float*)d_in[0];
    const float* Wq  = (const float*)d_in[1];
    const float* rel = (const float*)d_in[2];
    float* out = (float*)d_out;

    const int qp_smem = (2 * 128 * LDK + 2 * 64 * LDK) * 2;            // 55296
    const int at_smem = (2 * 128 * LDK + 2 * 2 * 64 * LDK) * 2 + 768;  // 74496
    cudaFuncSetAttribute(qproj_tc,  cudaFuncAttributeMaxDynamicSharedMemorySize, qp_smem);
    cudaFuncSetAttribute(attn_chunk, cudaFuncAttributeMaxDynamicSharedMemorySize, at_smem);

    qproj_tc<<<Bv * Tv / 128, 256, qp_smem>>>(x, Wq);
    attn_chunk<<<dim3(16, Bv, NCH), 256, at_smem>>>(rel);
    attn_combine<<<dim3(16, Bv, 8), 256>>>(out);
}